// round 1
// baseline (speedup 1.0000x reference)
#include <cuda_runtime.h>

#define N_NODES 100000
#define N_EDGES 400000
#define BATCH   2048
#define HD      128     // H*D
#define KID     100     // id_embed dim
#define NREL    100     // 2*NUM_REL

// ---------------- scratch (static device globals; no allocs) ----------------
__device__ float    g_h[(size_t)N_NODES * HD];     // node projections (51.2 MB)
__device__ float    g_ssrc[N_NODES * 2];           // h[n] . att_src  per head
__device__ float    g_sdst[N_NODES * 2];           // h[n] . att_dst  per head
__device__ float    g_rproj[NREL * HD];            // init_rel @ Wr
__device__ float    g_srel[NREL * 2];              // r_proj . att_src per head
__device__ float    g_catproj[23 * HD];            // gender(3)/age(9)/level(11) @ W slices
__device__ unsigned g_menc[N_NODES * 2];           // encoded per-dst max logits
__device__ float    g_den[N_NODES * 2];            // softmax denominators
__device__ float    g_ex[(size_t)N_EDGES * 2];     // logits, then exp(logit-max)

// monotonic float<->uint encoding for atomicMax on signed floats
__device__ __forceinline__ unsigned enc_f(float f) {
    unsigned u = __float_as_uint(f);
    return (u & 0x80000000u) ? ~u : (u | 0x80000000u);
}
__device__ __forceinline__ float dec_f(unsigned u) {
    return (u & 0x80000000u) ? __uint_as_float(u ^ 0x80000000u) : __uint_as_float(~u);
}

// ---------------- kernels ----------------

// zero x-accumulator region of d_out, den, and m_enc (0 encodes "below -inf")
__global__ void k_init(float* __restrict__ xout) {
    long i = (long)blockIdx.x * blockDim.x + threadIdx.x;
    if (i < (long)N_NODES * HD) xout[i] = 0.0f;
    if (i < N_NODES * 2) { g_menc[i] = 0u; g_den[i] = 0.0f; }
}

// 23 rows: gender_tab @ W[100:200], age_tab @ W[200:300], level_tab @ W[300:400]
__global__ void k_catproj(const float* __restrict__ gtab, const float* __restrict__ atab,
                          const float* __restrict__ ltab, const float* __restrict__ W) {
    int row = blockIdx.x;
    int d   = threadIdx.x;
    const float* tab;
    int base;
    if (row < 3)       { tab = gtab + row * 100;       base = 100; }
    else if (row < 12) { tab = atab + (row - 3) * 100; base = 200; }
    else               { tab = ltab + (row - 12) * 100; base = 300; }
    float acc = 0.0f;
#pragma unroll 4
    for (int k = 0; k < 100; k++) acc += tab[k] * W[(base + k) * HD + d];
    g_catproj[row * HD + d] = acc;
}

// r_proj = init_rel @ Wr  (+ s_rel = r_proj . att_src per head)
__global__ void k_rproj(const float* __restrict__ init_rel, const float* __restrict__ Wr,
                        const float* __restrict__ att_src) {
    int t = blockIdx.x;
    int d = threadIdx.x;
    const float* r = init_rel + t * 400;
    float acc = 0.0f;
#pragma unroll 8
    for (int k = 0; k < 400; k++) acc += r[k] * Wr[k * HD + d];
    g_rproj[t * HD + d] = acc;

    float p = acc * att_src[d];
#pragma unroll
    for (int o = 16; o > 0; o >>= 1) p += __shfl_xor_sync(0xffffffffu, p, o);
    __shared__ float ws[4];
    if ((d & 31) == 0) ws[d >> 5] = p;
    __syncthreads();
    if (d == 0)  g_srel[t * 2 + 0] = ws[0] + ws[1];
    if (d == 64) g_srel[t * 2 + 1] = ws[2] + ws[3];
}

// r_out = init_rel @ Wrel -> d_out r region
__global__ void k_rout(const float* __restrict__ init_rel, const float* __restrict__ Wrel,
                       float* __restrict__ rout) {
    int t = blockIdx.x;
    int d = threadIdx.x;
    const float* r = init_rel + t * 400;
    float acc = 0.0f;
#pragma unroll 8
    for (int k = 0; k < 400; k++) acc += r[k] * Wrel[k * HD + d];
    rout[t * HD + d] = acc;
}

// h[n] = id_embed[n] @ W[:100] + cat lookups; also s_src/s_dst per head
// block: 128 threads, 4 nodes per iteration, W[:100] + cat tables in smem
__global__ void k_h(const float* __restrict__ id_embed, const int* __restrict__ ent_feature,
                    const float* __restrict__ W, const float* __restrict__ att_src,
                    const float* __restrict__ att_dst) {
    extern __shared__ float sm[];
    float* Ws  = sm;            // 12800 floats: W[0:100, 0:128]
    float* cat = Ws + 12800;    // 2944 floats
    float* sx  = cat + 2944;    // 400 floats: 4 id_embed rows (16B aligned)
    float* red = sx + 400;      // 8 floats reduce scratch

    const int tid = threadIdx.x;
    for (int i = tid; i < 12800; i += 128) Ws[i] = W[i];
    for (int i = tid; i < 23 * HD; i += 128) cat[i] = g_catproj[i];
    const float a_s = att_src[tid];
    const float a_d = att_dst[tid];
    __syncthreads();

    const int nquads = N_NODES / 4;  // 25000, N divisible by 4
    for (int q = blockIdx.x; q < nquads; q += gridDim.x) {
        const int n0 = q * 4;
        __syncthreads();  // protect sx reuse across iterations
        for (int i = tid; i < 400; i += 128) sx[i] = id_embed[(long)n0 * KID + i];
        __syncthreads();

        float acc0 = 0.f, acc1 = 0.f, acc2 = 0.f, acc3 = 0.f;
        for (int k = 0; k < 100; k += 4) {
            float4 x0 = *(const float4*)&sx[k];
            float4 x1 = *(const float4*)&sx[100 + k];
            float4 x2 = *(const float4*)&sx[200 + k];
            float4 x3 = *(const float4*)&sx[300 + k];
            float w0 = Ws[(k + 0) * 128 + tid];
            float w1 = Ws[(k + 1) * 128 + tid];
            float w2 = Ws[(k + 2) * 128 + tid];
            float w3 = Ws[(k + 3) * 128 + tid];
            acc0 += x0.x * w0; acc1 += x1.x * w0; acc2 += x2.x * w0; acc3 += x3.x * w0;
            acc0 += x0.y * w1; acc1 += x1.y * w1; acc2 += x2.y * w1; acc3 += x3.y * w1;
            acc0 += x0.z * w2; acc1 += x1.z * w2; acc2 += x2.z * w2; acc3 += x3.z * w2;
            acc0 += x0.w * w3; acc1 += x1.w * w3; acc2 += x2.w * w3; acc3 += x3.w * w3;
        }
        float accs[4] = {acc0, acc1, acc2, acc3};
#pragma unroll
        for (int i = 0; i < 4; i++) {
            const int n  = n0 + i;
            const int gf = ent_feature[n * 3 + 0];
            const int af = ent_feature[n * 3 + 1];
            const int lf = ent_feature[n * 3 + 2];
            float hv = accs[i] + cat[gf * 128 + tid] + cat[(3 + af) * 128 + tid]
                               + cat[(12 + lf) * 128 + tid];
            g_h[(long)n * HD + tid] = hv;

            float ps = hv * a_s, pd = hv * a_d;
#pragma unroll
            for (int o = 16; o > 0; o >>= 1) {
                ps += __shfl_xor_sync(0xffffffffu, ps, o);
                pd += __shfl_xor_sync(0xffffffffu, pd, o);
            }
            const int w = tid >> 5;
            if ((tid & 31) == 0) { red[w] = ps; red[4 + w] = pd; }
            __syncthreads();
            if (tid == 0)  { g_ssrc[n * 2 + 0] = red[0] + red[1]; g_sdst[n * 2 + 0] = red[4] + red[5]; }
            if (tid == 64) { g_ssrc[n * 2 + 1] = red[2] + red[3]; g_sdst[n * 2 + 1] = red[6] + red[7]; }
            __syncthreads();
        }
    }
}

// per-edge logits + per-dst encoded atomic max
__global__ void k_logit(const int* __restrict__ edge_index, const int* __restrict__ edge_type) {
    int e = blockIdx.x * blockDim.x + threadIdx.x;
    if (e >= N_EDGES) return;
    const int src = edge_index[e];
    const int dst = edge_index[N_EDGES + e];
    const int et  = edge_type[e];
#pragma unroll
    for (int h = 0; h < 2; h++) {
        float l = g_ssrc[src * 2 + h] + g_srel[et * 2 + h] + g_sdst[dst * 2 + h];
        l = (l > 0.0f) ? l : 0.2f * l;  // leaky_relu(0.2)
        g_ex[(size_t)e * 2 + h] = l;
        atomicMax(&g_menc[dst * 2 + h], enc_f(l));
    }
}

// exp(logit - max) + denominator accumulation
__global__ void k_den(const int* __restrict__ edge_index) {
    int e = blockIdx.x * blockDim.x + threadIdx.x;
    if (e >= N_EDGES) return;
    const int dst = edge_index[N_EDGES + e];
#pragma unroll
    for (int h = 0; h < 2; h++) {
        float m  = dec_f(g_menc[dst * 2 + h]);
        float ex = __expf(g_ex[(size_t)e * 2 + h] - m);
        g_ex[(size_t)e * 2 + h] = ex;
        atomicAdd(&g_den[dst * 2 + h], ex);
    }
}

// weighted message aggregation: atomicAdd alpha*(h[src]+r_proj[et]) into x region
__global__ void k_acc(const int* __restrict__ edge_index, const int* __restrict__ edge_type,
                      float* __restrict__ xout) {
    long idx = (long)blockIdx.x * 256 + threadIdx.x;
    int e = (int)(idx >> 7);
    int d = (int)(idx & 127);
    if (e >= N_EDGES) return;
    const int src = edge_index[e];
    const int dst = edge_index[N_EDGES + e];
    const int et  = edge_type[e];
    const int h   = d >> 6;
    float alpha = g_ex[(size_t)e * 2 + h] / (g_den[dst * 2 + h] + 1e-16f);
    float v = alpha * (g_h[(long)src * HD + d] + g_rproj[et * HD + d]);
    atomicAdd(&xout[(long)dst * HD + d], v);
}

// in-place tanh over x region
__global__ void k_tanh(float* __restrict__ xout) {
    long i = (long)blockIdx.x * blockDim.x + threadIdx.x;
    if (i < (long)N_NODES * HD) xout[i] = tanhf(xout[i]);
}

// sub gather
__global__ void k_gather(const int* __restrict__ sub, const float* __restrict__ xout,
                         float* __restrict__ sub_emb) {
    int b = blockIdx.x;
    int d = threadIdx.x;
    sub_emb[(long)b * HD + d] = xout[(long)sub[b] * HD + d];
}

// ---------------- launch ----------------
extern "C" void kernel_launch(void* const* d_in, const int* in_sizes, int n_in,
                              void* d_out, int out_size) {
    const int*   edge_index  = (const int*)d_in[0];
    const int*   edge_type   = (const int*)d_in[1];
    // d_in[2] edge_type_p unused
    const int*   ent_feature = (const int*)d_in[3];
    const int*   sub         = (const int*)d_in[4];
    // d_in[5] rel, d_in[6] relp unused
    const float* id_embed    = (const float*)d_in[7];
    const float* gender_tab  = (const float*)d_in[8];
    const float* age_tab     = (const float*)d_in[9];
    const float* level_tab   = (const float*)d_in[10];
    const float* init_rel    = (const float*)d_in[11];
    const float* W           = (const float*)d_in[12];
    const float* Wr          = (const float*)d_in[13];
    const float* att_src     = (const float*)d_in[14];
    const float* att_dst     = (const float*)d_in[15];
    const float* Wrel        = (const float*)d_in[16];

    float* out     = (float*)d_out;
    float* sub_emb = out;                          // [2048,128]
    float* rout    = out + (long)BATCH * HD;       // [100,128]
    float* xout    = rout + (long)NREL * HD;       // [100000,128]

    // dynamic smem for k_h: (12800 + 2944 + 400 + 8) floats = 64608 B
    const int smem_kh = (12800 + 2944 + 400 + 8) * (int)sizeof(float);
    cudaFuncSetAttribute(k_h, cudaFuncAttributeMaxDynamicSharedMemorySize, smem_kh);

    const long xtot = (long)N_NODES * HD;  // 12,800,000
    k_init<<<(int)((xtot + 255) / 256), 256>>>(xout);
    k_catproj<<<23, 128>>>(gender_tab, age_tab, level_tab, W);
    k_rproj<<<NREL, 128>>>(init_rel, Wr, att_src);
    k_rout<<<NREL, 128>>>(init_rel, Wrel, rout);
    k_h<<<888, 128, smem_kh>>>(id_embed, ent_feature, W, att_src, att_dst);
    k_logit<<<(N_EDGES + 255) / 256, 256>>>(edge_index, edge_type);
    k_den<<<(N_EDGES + 255) / 256, 256>>>(edge_index);
    k_acc<<<(int)(((long)N_EDGES * HD + 255) / 256), 256>>>(edge_index, edge_type, xout);
    k_tanh<<<(int)((xtot + 255) / 256), 256>>>(xout);
    k_gather<<<BATCH, 128>>>(sub, xout, sub_emb);
}

// round 2
// speedup vs baseline: 1.5231x; 1.5231x over previous
#include <cuda_runtime.h>

#define N_NODES 100000
#define N_EDGES 400000
#define BATCH   2048
#define HD      128     // H*D
#define NREL    100     // 2*NUM_REL

// ---------------- scratch (static device globals; no allocs) ----------------
__device__ __align__(16) float    g_h[(size_t)N_NODES * HD];   // node projections (51.2 MB)
__device__ __align__(16) float    g_ssrc[N_NODES * 2];         // h . att_src per head
__device__ __align__(16) float    g_sdst[N_NODES * 2];         // h . att_dst per head
__device__ __align__(16) float    g_rproj[NREL * HD];          // init_rel @ Wr
__device__ __align__(16) float    g_srel[NREL * 2];            // r_proj . att_src per head
__device__ __align__(16) float    g_catproj[23 * HD];          // cat tables @ W slices
__device__ __align__(16) unsigned g_menc[N_NODES * 2];         // encoded per-dst max
__device__ __align__(16) float    g_den[N_NODES * 2];          // softmax denominators
__device__ __align__(16) float    g_ex[(size_t)N_EDGES * 2];   // logits -> exp -> alpha

__device__ __forceinline__ unsigned enc_f(float f) {
    unsigned u = __float_as_uint(f);
    return (u & 0x80000000u) ? ~u : (u | 0x80000000u);
}
__device__ __forceinline__ float dec_f(unsigned u) {
    return (u & 0x80000000u) ? __uint_as_float(u ^ 0x80000000u) : __uint_as_float(~u);
}
__device__ __forceinline__ float tanh_approx(float x) {
    float y;
    asm("tanh.approx.f32 %0, %1;" : "=f"(y) : "f"(x));
    return y;
}

// ---------------- fused prep: small GEMMs (K-split) + zero init ----------------
// blocks [0,100):   g_rproj row = init_rel[b] @ Wr   (+ g_srel)
// blocks [100,200): rout row    = init_rel[b-100] @ Wrel
// blocks [200,223): g_catproj   = cat tables @ W slices
// blocks [223,...): zero xout / g_menc / g_den
__global__ void k_prep(const float* __restrict__ gtab, const float* __restrict__ atab,
                       const float* __restrict__ ltab, const float* __restrict__ init_rel,
                       const float* __restrict__ W,    const float* __restrict__ Wr,
                       const float* __restrict__ Wrel, const float* __restrict__ att_src,
                       float* __restrict__ rout, float* __restrict__ xout) {
    const int b   = blockIdx.x;
    const int tid = threadIdx.x;  // 512

    if (b >= 223) {
        const long NX4 = (long)N_NODES * HD / 4;  // 3,200,000
        const long NM4 = N_NODES * 2 / 4;         // 50,000
        const long TOT = NX4 + 2 * NM4;
        const float4 z = make_float4(0.f, 0.f, 0.f, 0.f);
        const long stride = (long)(gridDim.x - 223) * 512;
        for (long i = (long)(b - 223) * 512 + tid; i < TOT; i += stride) {
            if (i < NX4)            ((float4*)xout)[i] = z;
            else if (i < NX4 + NM4) ((uint4*)g_menc)[i - NX4] = make_uint4(0u, 0u, 0u, 0u);
            else                    ((float4*)g_den)[i - NX4 - NM4] = z;
        }
        return;
    }

    const int d = tid & 127;
    const int s = tid >> 7;  // k-slice 0..3
    const float* arow;
    const float* Bmat;
    int klen;
    if (b < 100)       { arow = init_rel + b * 400;         Bmat = Wr;   klen = 400; }
    else if (b < 200)  { arow = init_rel + (b - 100) * 400; Bmat = Wrel; klen = 400; }
    else {
        int c = b - 200;
        if (c < 3)       { arow = gtab + c * 100;        Bmat = W + 100 * HD; }
        else if (c < 12) { arow = atab + (c - 3) * 100;  Bmat = W + 200 * HD; }
        else             { arow = ltab + (c - 12) * 100; Bmat = W + 300 * HD; }
        klen = 100;
    }
    const int span = klen >> 2;
    const int k0   = s * span;
    float acc = 0.f;
#pragma unroll 5
    for (int k = k0; k < k0 + span; k++) acc += arow[k] * Bmat[k * HD + d];

    __shared__ float part[512];
    part[tid] = acc;
    __syncthreads();
    float total = 0.f;
    if (tid < 128) {
        total = part[tid] + part[tid + 128] + part[tid + 256] + part[tid + 384];
        if (b < 100)      g_rproj[b * HD + d] = total;
        else if (b < 200) rout[(b - 100) * HD + d] = total;
        else              g_catproj[(b - 200) * HD + d] = total;
    }
    if (b < 100) {
        float p = (tid < 128) ? total * att_src[d] : 0.f;
#pragma unroll
        for (int o = 16; o > 0; o >>= 1) p += __shfl_xor_sync(0xffffffffu, p, o);
        __shared__ float ws[16];
        if ((tid & 31) == 0) ws[tid >> 5] = p;
        __syncthreads();
        if (tid == 0) {
            g_srel[b * 2 + 0] = ws[0] + ws[1];
            g_srel[b * 2 + 1] = ws[2] + ws[3];
        }
    }
}

// ---------------- h = id_embed @ W[:100] + cat lookups; plus score dots ----------------
__global__ void k_h(const float* __restrict__ id_embed, const int* __restrict__ ent_feature,
                    const float* __restrict__ W, const float* __restrict__ att_src,
                    const float* __restrict__ att_dst) {
    extern __shared__ float sm[];
    float* Ws  = sm;            // 12800: W[0:100, :]
    float* cat = Ws + 12800;    // 2944
    float* sx  = cat + 2944;    // 400: 4 id_embed rows
    float* red = sx + 400;      // 32: 4 nodes x {ps,pd} x 4 warps

    const int tid  = threadIdx.x;
    const int lane = tid & 31;
    const int w    = tid >> 5;
    for (int i = tid; i < 12800; i += 128) Ws[i] = W[i];
    for (int i = tid; i < 23 * HD; i += 128) cat[i] = g_catproj[i];
    const float a_s = att_src[tid];
    const float a_d = att_dst[tid];
    __syncthreads();

    for (int q = blockIdx.x; q < N_NODES / 4; q += gridDim.x) {
        const int n0 = q * 4;
        __syncthreads();
        for (int i = tid; i < 400; i += 128) sx[i] = id_embed[(long)n0 * 100 + i];
        __syncthreads();

        float acc0 = 0.f, acc1 = 0.f, acc2 = 0.f, acc3 = 0.f;
#pragma unroll
        for (int k = 0; k < 100; k += 4) {
            float4 x0 = *(const float4*)&sx[k];
            float4 x1 = *(const float4*)&sx[100 + k];
            float4 x2 = *(const float4*)&sx[200 + k];
            float4 x3 = *(const float4*)&sx[300 + k];
            float w0 = Ws[(k + 0) * 128 + tid];
            float w1 = Ws[(k + 1) * 128 + tid];
            float w2 = Ws[(k + 2) * 128 + tid];
            float w3 = Ws[(k + 3) * 128 + tid];
            acc0 += x0.x * w0; acc1 += x1.x * w0; acc2 += x2.x * w0; acc3 += x3.x * w0;
            acc0 += x0.y * w1; acc1 += x1.y * w1; acc2 += x2.y * w1; acc3 += x3.y * w1;
            acc0 += x0.z * w2; acc1 += x1.z * w2; acc2 += x2.z * w2; acc3 += x3.z * w2;
            acc0 += x0.w * w3; acc1 += x1.w * w3; acc2 += x2.w * w3; acc3 += x3.w * w3;
        }
        float accs[4] = {acc0, acc1, acc2, acc3};
#pragma unroll
        for (int i = 0; i < 4; i++) {
            const int n  = n0 + i;
            const int gf = ent_feature[n * 3 + 0];
            const int af = ent_feature[n * 3 + 1];
            const int lf = ent_feature[n * 3 + 2];
            float hv = accs[i] + cat[gf * 128 + tid] + cat[(3 + af) * 128 + tid]
                               + cat[(12 + lf) * 128 + tid];
            g_h[(long)n * HD + tid] = hv;

            float ps = hv * a_s, pd = hv * a_d;
#pragma unroll
            for (int o = 16; o > 0; o >>= 1) {
                ps += __shfl_xor_sync(0xffffffffu, ps, o);
                pd += __shfl_xor_sync(0xffffffffu, pd, o);
            }
            if (lane == 0) { red[i * 8 + w] = ps; red[i * 8 + 4 + w] = pd; }
        }
        __syncthreads();
        if (tid < 16) {
            const int i = tid >> 2, sel = tid & 3;
            const int n = n0 + i;
            const float* base = red + i * 8;
            if (sel == 0)      g_ssrc[n * 2 + 0] = base[0] + base[1];
            else if (sel == 1) g_ssrc[n * 2 + 1] = base[2] + base[3];
            else if (sel == 2) g_sdst[n * 2 + 0] = base[4] + base[5];
            else               g_sdst[n * 2 + 1] = base[6] + base[7];
        }
    }
}

// ---------------- edge passes ----------------
__global__ void k_logit(const int* __restrict__ ei, const int* __restrict__ etyp) {
    int e = blockIdx.x * 256 + threadIdx.x;
    if (e >= N_EDGES) return;
    const int src = ei[e];
    const int dst = ei[N_EDGES + e];
    const int et  = etyp[e];
    float2 ss = ((const float2*)g_ssrc)[src];
    float2 sr = ((const float2*)g_srel)[et];
    float2 sd = ((const float2*)g_sdst)[dst];
    float l0 = ss.x + sr.x + sd.x; l0 = (l0 > 0.f) ? l0 : 0.2f * l0;
    float l1 = ss.y + sr.y + sd.y; l1 = (l1 > 0.f) ? l1 : 0.2f * l1;
    ((float2*)g_ex)[e] = make_float2(l0, l1);
    atomicMax(&g_menc[dst * 2 + 0], enc_f(l0));
    atomicMax(&g_menc[dst * 2 + 1], enc_f(l1));
}

__global__ void k_den(const int* __restrict__ ei) {
    int e = blockIdx.x * 256 + threadIdx.x;
    if (e >= N_EDGES) return;
    const int dst = ei[N_EDGES + e];
    uint2  me = ((const uint2*)g_menc)[dst];
    float2 l  = ((const float2*)g_ex)[e];
    float e0 = __expf(l.x - dec_f(me.x));
    float e1 = __expf(l.y - dec_f(me.y));
    ((float2*)g_ex)[e] = make_float2(e0, e1);
    atomicAdd(&g_den[dst * 2 + 0], e0);
    atomicAdd(&g_den[dst * 2 + 1], e1);
}

__global__ void k_alpha(const int* __restrict__ ei) {
    int e = blockIdx.x * 256 + threadIdx.x;
    if (e >= N_EDGES) return;
    const int dst = ei[N_EDGES + e];
    float2 den = ((const float2*)g_den)[dst];
    float2 ex  = ((const float2*)g_ex)[e];
    ex.x = ex.x / (den.x + 1e-16f);
    ex.y = ex.y / (den.y + 1e-16f);
    ((float2*)g_ex)[e] = ex;
}

// weighted aggregation: each thread handles 4 dims of one edge
__global__ void k_acc(const int* __restrict__ ei, const int* __restrict__ etyp,
                      float* __restrict__ xout) {
    long idx = (long)blockIdx.x * 256 + threadIdx.x;  // E*32 total
    const int e  = (int)(idx >> 5);
    const int d  = (int)(idx & 31) << 2;
    const int src = ei[e];
    const int dst = ei[N_EDGES + e];
    const int et  = etyp[e];
    const float alpha = __ldg(&g_ex[(size_t)e * 2 + (d >> 6)]);
    float4 hv = *(const float4*)&g_h[(long)src * HD + d];
    float4 rv = *(const float4*)&g_rproj[et * HD + d];
    float* o = &xout[(long)dst * HD + d];
    atomicAdd(o + 0, alpha * (hv.x + rv.x));
    atomicAdd(o + 1, alpha * (hv.y + rv.y));
    atomicAdd(o + 2, alpha * (hv.z + rv.z));
    atomicAdd(o + 3, alpha * (hv.w + rv.w));
}

__global__ void k_tanh(float* __restrict__ xout) {
    long i = (long)blockIdx.x * 256 + threadIdx.x;  // over 3.2M float4
    float4 v = ((float4*)xout)[i];
    v.x = tanh_approx(v.x);
    v.y = tanh_approx(v.y);
    v.z = tanh_approx(v.z);
    v.w = tanh_approx(v.w);
    ((float4*)xout)[i] = v;
}

__global__ void k_gather(const int* __restrict__ sub, const float* __restrict__ xout,
                         float* __restrict__ sub_emb) {
    int b = blockIdx.x;
    int d = threadIdx.x;
    sub_emb[(long)b * HD + d] = xout[(long)sub[b] * HD + d];
}

// ---------------- launch ----------------
extern "C" void kernel_launch(void* const* d_in, const int* in_sizes, int n_in,
                              void* d_out, int out_size) {
    const int*   edge_index  = (const int*)d_in[0];
    const int*   edge_type   = (const int*)d_in[1];
    const int*   ent_feature = (const int*)d_in[3];
    const int*   sub         = (const int*)d_in[4];
    const float* id_embed    = (const float*)d_in[7];
    const float* gender_tab  = (const float*)d_in[8];
    const float* age_tab     = (const float*)d_in[9];
    const float* level_tab   = (const float*)d_in[10];
    const float* init_rel    = (const float*)d_in[11];
    const float* W           = (const float*)d_in[12];
    const float* Wr          = (const float*)d_in[13];
    const float* att_src     = (const float*)d_in[14];
    const float* att_dst     = (const float*)d_in[15];
    const float* Wrel        = (const float*)d_in[16];

    float* out     = (float*)d_out;
    float* sub_emb = out;                      // [2048,128]
    float* rout    = out + (long)BATCH * HD;   // [100,128]
    float* xout    = rout + (long)NREL * HD;   // [100000,128]

    const int smem_kh = (12800 + 2944 + 400 + 32) * (int)sizeof(float);  // 64704
    cudaFuncSetAttribute(k_h, cudaFuncAttributeMaxDynamicSharedMemorySize, smem_kh);

    k_prep<<<223 + 480, 512>>>(gender_tab, age_tab, level_tab, init_rel, W, Wr, Wrel,
                               att_src, rout, xout);
    k_h<<<444, 128, smem_kh>>>(id_embed, ent_feature, W, att_src, att_dst);
    k_logit<<<(N_EDGES + 255) / 256, 256>>>(edge_index, edge_type);
    k_den<<<(N_EDGES + 255) / 256, 256>>>(edge_index);
    k_alpha<<<(N_EDGES + 255) / 256, 256>>>(edge_index);
    k_acc<<<(N_EDGES * 32) / 256, 256>>>(edge_index, edge_type, xout);
    k_tanh<<<(N_NODES * HD / 4) / 256, 256>>>(xout);
    k_gather<<<BATCH, 128>>>(sub, xout, sub_emb);
}

// round 3
// speedup vs baseline: 1.6942x; 1.1123x over previous
#include <cuda_runtime.h>

#define N_NODES 100000
#define N_EDGES 400000
#define BATCH   2048
#define HD      128
#define NREL    100

// ---------------- scratch ----------------
__device__ __align__(16) float g_h[(size_t)N_NODES * HD];
__device__ __align__(16) float g_ssrc[N_NODES * 2];
__device__ __align__(16) float g_sdst[N_NODES * 2];
__device__ __align__(16) float g_rproj[NREL * HD];
__device__ __align__(16) float g_srel[NREL * 2];
__device__ __align__(16) float g_catproj[23 * HD];
__device__ __align__(16) int   g_deg[N_NODES];      // degree counts
__device__ __align__(16) int   g_off[N_NODES + 1];  // CSR offsets
__device__ __align__(16) int   g_cur[N_NODES];      // scatter cursors
__device__ __align__(16) int   g_esrc[N_EDGES];     // dst-sorted src
__device__ __align__(16) int   g_eet[N_EDGES];      // dst-sorted edge type
__device__ int g_bsum[128];                         // scan block sums

__device__ __forceinline__ float tanh_approx(float x) {
    float y;
    asm("tanh.approx.f32 %0, %1;" : "=f"(y) : "f"(x));
    return y;
}

// ---------------- prep: small GEMMs (K-split) + zero degree counters ----------------
__global__ void k_prep(const float* __restrict__ gtab, const float* __restrict__ atab,
                       const float* __restrict__ ltab, const float* __restrict__ init_rel,
                       const float* __restrict__ W,    const float* __restrict__ Wr,
                       const float* __restrict__ Wrel, const float* __restrict__ att_src,
                       float* __restrict__ rout) {
    const int b   = blockIdx.x;
    const int tid = threadIdx.x;  // 512

    if (b >= 223) {  // zero g_deg: 25000 int4
        int i = (b - 223) * 512 + tid;
        if (i < N_NODES / 4) ((int4*)g_deg)[i] = make_int4(0, 0, 0, 0);
        return;
    }

    const int d = tid & 127;
    const int s = tid >> 7;
    const float* arow;
    const float* Bmat;
    int klen;
    if (b < 100)       { arow = init_rel + b * 400;         Bmat = Wr;   klen = 400; }
    else if (b < 200)  { arow = init_rel + (b - 100) * 400; Bmat = Wrel; klen = 400; }
    else {
        int c = b - 200;
        if (c < 3)       { arow = gtab + c * 100;        Bmat = W + 100 * HD; }
        else if (c < 12) { arow = atab + (c - 3) * 100;  Bmat = W + 200 * HD; }
        else             { arow = ltab + (c - 12) * 100; Bmat = W + 300 * HD; }
        klen = 100;
    }
    const int span = klen >> 2;
    const int k0   = s * span;
    float acc = 0.f;
#pragma unroll 5
    for (int k = k0; k < k0 + span; k++) acc += arow[k] * Bmat[k * HD + d];

    __shared__ float part[512];
    part[tid] = acc;
    __syncthreads();
    float total = 0.f;
    if (tid < 128) {
        total = part[tid] + part[tid + 128] + part[tid + 256] + part[tid + 384];
        if (b < 100)      g_rproj[b * HD + d] = total;
        else if (b < 200) rout[(b - 100) * HD + d] = total;
        else              g_catproj[(b - 200) * HD + d] = total;
    }
    if (b < 100) {
        float p = (tid < 128) ? total * att_src[d] : 0.f;
#pragma unroll
        for (int o = 16; o > 0; o >>= 1) p += __shfl_xor_sync(0xffffffffu, p, o);
        __shared__ float ws[16];
        if ((tid & 31) == 0) ws[tid >> 5] = p;
        __syncthreads();
        if (tid == 0) {
            g_srel[b * 2 + 0] = ws[0] + ws[1];
            g_srel[b * 2 + 1] = ws[2] + ws[3];
        }
    }
}

// ---------------- h projection + attention score scalars ----------------
__global__ void k_h(const float* __restrict__ id_embed, const int* __restrict__ ent_feature,
                    const float* __restrict__ W, const float* __restrict__ att_src,
                    const float* __restrict__ att_dst) {
    extern __shared__ float sm[];
    float* Ws  = sm;          // 12800
    float* cat = Ws + 12800;  // 2944
    float* sx  = cat + 2944;  // 400
    float* red = sx + 400;    // 32

    const int tid  = threadIdx.x;
    const int lane = tid & 31;
    const int w    = tid >> 5;
    for (int i = tid; i < 12800; i += 128) Ws[i] = W[i];
    for (int i = tid; i < 23 * HD; i += 128) cat[i] = g_catproj[i];
    const float a_s = att_src[tid];
    const float a_d = att_dst[tid];
    __syncthreads();

    for (int q = blockIdx.x; q < N_NODES / 4; q += gridDim.x) {
        const int n0 = q * 4;
        __syncthreads();
        for (int i = tid; i < 400; i += 128) sx[i] = id_embed[(long)n0 * 100 + i];
        __syncthreads();

        float acc0 = 0.f, acc1 = 0.f, acc2 = 0.f, acc3 = 0.f;
#pragma unroll
        for (int k = 0; k < 100; k += 4) {
            float4 x0 = *(const float4*)&sx[k];
            float4 x1 = *(const float4*)&sx[100 + k];
            float4 x2 = *(const float4*)&sx[200 + k];
            float4 x3 = *(const float4*)&sx[300 + k];
            float w0 = Ws[(k + 0) * 128 + tid];
            float w1 = Ws[(k + 1) * 128 + tid];
            float w2 = Ws[(k + 2) * 128 + tid];
            float w3 = Ws[(k + 3) * 128 + tid];
            acc0 += x0.x * w0; acc1 += x1.x * w0; acc2 += x2.x * w0; acc3 += x3.x * w0;
            acc0 += x0.y * w1; acc1 += x1.y * w1; acc2 += x2.y * w1; acc3 += x3.y * w1;
            acc0 += x0.z * w2; acc1 += x1.z * w2; acc2 += x2.z * w2; acc3 += x3.z * w2;
            acc0 += x0.w * w3; acc1 += x1.w * w3; acc2 += x2.w * w3; acc3 += x3.w * w3;
        }
        float accs[4] = {acc0, acc1, acc2, acc3};
#pragma unroll
        for (int i = 0; i < 4; i++) {
            const int n  = n0 + i;
            const int gf = ent_feature[n * 3 + 0];
            const int af = ent_feature[n * 3 + 1];
            const int lf = ent_feature[n * 3 + 2];
            float hv = accs[i] + cat[gf * 128 + tid] + cat[(3 + af) * 128 + tid]
                               + cat[(12 + lf) * 128 + tid];
            g_h[(long)n * HD + tid] = hv;

            float ps = hv * a_s, pd = hv * a_d;
#pragma unroll
            for (int o = 16; o > 0; o >>= 1) {
                ps += __shfl_xor_sync(0xffffffffu, ps, o);
                pd += __shfl_xor_sync(0xffffffffu, pd, o);
            }
            if (lane == 0) { red[i * 8 + w] = ps; red[i * 8 + 4 + w] = pd; }
        }
        __syncthreads();
        if (tid < 16) {
            const int i = tid >> 2, sel = tid & 3;
            const int n = n0 + i;
            const float* base = red + i * 8;
            if (sel == 0)      g_ssrc[n * 2 + 0] = base[0] + base[1];
            else if (sel == 1) g_ssrc[n * 2 + 1] = base[2] + base[3];
            else if (sel == 2) g_sdst[n * 2 + 0] = base[4] + base[5];
            else               g_sdst[n * 2 + 1] = base[6] + base[7];
        }
    }
}

// ---------------- CSR build ----------------
__global__ void k_deg(const int* __restrict__ ei) {
    int e = blockIdx.x * 256 + threadIdx.x;
    if (e < N_EDGES) atomicAdd(&g_deg[ei[N_EDGES + e]], 1);
}

// 100 blocks x 1000 elems: block sums
__global__ void k_scan1() {
    __shared__ int sred[256];
    const int tid = threadIdx.x;
    const int base = blockIdx.x * 1000;
    int s = 0;
    for (int i = tid; i < 1000; i += 256) s += g_deg[base + i];
    sred[tid] = s;
    __syncthreads();
    for (int o = 128; o > 0; o >>= 1) {
        if (tid < o) sred[tid] += sred[tid + o];
        __syncthreads();
    }
    if (tid == 0) g_bsum[blockIdx.x] = sred[0];
}

// single block: exclusive scan of 100 block sums
__global__ void k_scan2() {
    if (threadIdx.x == 0) {
        int run = 0;
        for (int b = 0; b < 100; b++) { int v = g_bsum[b]; g_bsum[b] = run; run += v; }
        g_off[N_NODES] = N_EDGES;
    }
}

// 100 blocks: exclusive scan within chunk, write off + cur
__global__ void k_scan3() {
    __shared__ int ts[256];
    __shared__ int vals[1000];
    const int tid  = threadIdx.x;
    const int base = blockIdx.x * 1000;
    // each of 250 threads handles 4 consecutive
    int v0 = 0, v1 = 0, v2 = 0, v3 = 0, tsum = 0;
    if (tid < 250) {
        v0 = g_deg[base + tid * 4 + 0];
        v1 = g_deg[base + tid * 4 + 1];
        v2 = g_deg[base + tid * 4 + 2];
        v3 = g_deg[base + tid * 4 + 3];
        tsum = v0 + v1 + v2 + v3;
    }
    ts[tid] = tsum;
    __syncthreads();
    // inclusive Hillis-Steele over 256
    for (int o = 1; o < 256; o <<= 1) {
        int add = (tid >= o) ? ts[tid - o] : 0;
        __syncthreads();
        ts[tid] += add;
        __syncthreads();
    }
    if (tid < 250) {
        int excl = ts[tid] - tsum + g_bsum[blockIdx.x];
        vals[tid * 4 + 0] = excl;
        vals[tid * 4 + 1] = excl + v0;
        vals[tid * 4 + 2] = excl + v0 + v1;
        vals[tid * 4 + 3] = excl + v0 + v1 + v2;
    }
    __syncthreads();
    for (int i = tid; i < 1000; i += 256) {
        g_off[base + i] = vals[i];
        g_cur[base + i] = vals[i];
    }
}

__global__ void k_scatter(const int* __restrict__ ei, const int* __restrict__ etyp) {
    int e = blockIdx.x * 256 + threadIdx.x;
    if (e >= N_EDGES) return;
    const int dst = ei[N_EDGES + e];
    int pos = atomicAdd(&g_cur[dst], 1);
    g_esrc[pos] = ei[e];
    g_eet[pos]  = etyp[e];
}

// ---------------- fused per-dst softmax + aggregation + tanh ----------------
__global__ void k_agg(float* __restrict__ xout) {
    __shared__ float rp[NREL * HD];  // 51.2 KB
    const int tid = threadIdx.x;     // 256
    for (int i = tid; i < NREL * HD; i += 256) rp[i] = g_rproj[i];
    __syncthreads();

    const int lane = tid & 31;
    const int wid  = tid >> 5;
    const int head = lane >> 4;
    const int nwarps = gridDim.x * 8;

    for (int dst = blockIdx.x * 8 + wid; dst < N_NODES; dst += nwarps) {
        const int start = g_off[dst];
        const int end   = g_off[dst + 1];
        const float2 sd = ((const float2*)g_sdst)[dst];

        // pass 1: max logit per head
        float m0 = -1e30f, m1 = -1e30f;
        for (int i = start + lane; i < end; i += 32) {
            const int s = g_esrc[i], t = g_eet[i];
            float2 ss = ((const float2*)g_ssrc)[s];
            float2 sr = ((const float2*)g_srel)[t];
            float l0 = ss.x + sr.x + sd.x; l0 = (l0 > 0.f) ? l0 : 0.2f * l0;
            float l1 = ss.y + sr.y + sd.y; l1 = (l1 > 0.f) ? l1 : 0.2f * l1;
            m0 = fmaxf(m0, l0); m1 = fmaxf(m1, l1);
        }
#pragma unroll
        for (int o = 16; o > 0; o >>= 1) {
            m0 = fmaxf(m0, __shfl_xor_sync(0xffffffffu, m0, o));
            m1 = fmaxf(m1, __shfl_xor_sync(0xffffffffu, m1, o));
        }
        // pass 2: denominators
        float d0 = 0.f, d1 = 0.f;
        for (int i = start + lane; i < end; i += 32) {
            const int s = g_esrc[i], t = g_eet[i];
            float2 ss = ((const float2*)g_ssrc)[s];
            float2 sr = ((const float2*)g_srel)[t];
            float l0 = ss.x + sr.x + sd.x; l0 = (l0 > 0.f) ? l0 : 0.2f * l0;
            float l1 = ss.y + sr.y + sd.y; l1 = (l1 > 0.f) ? l1 : 0.2f * l1;
            d0 += __expf(l0 - m0); d1 += __expf(l1 - m1);
        }
#pragma unroll
        for (int o = 16; o > 0; o >>= 1) {
            d0 += __shfl_xor_sync(0xffffffffu, d0, o);
            d1 += __shfl_xor_sync(0xffffffffu, d1, o);
        }
        const float inv0 = 1.f / (d0 + 1e-16f);
        const float inv1 = 1.f / (d1 + 1e-16f);

        // pass 3: weighted aggregation, 32-edge chunks
        float4 acc = make_float4(0.f, 0.f, 0.f, 0.f);
        for (int base = start; base < end; base += 32) {
            const int i = base + lane;
            int s = 0, t = 0;
            float a0 = 0.f, a1 = 0.f;
            if (i < end) {
                s = g_esrc[i]; t = g_eet[i];
                float2 ss = ((const float2*)g_ssrc)[s];
                float2 sr = ((const float2*)g_srel)[t];
                float l0 = ss.x + sr.x + sd.x; l0 = (l0 > 0.f) ? l0 : 0.2f * l0;
                float l1 = ss.y + sr.y + sd.y; l1 = (l1 > 0.f) ? l1 : 0.2f * l1;
                a0 = __expf(l0 - m0) * inv0;
                a1 = __expf(l1 - m1) * inv1;
            }
            const int cnt = min(32, end - base);
            for (int j = 0; j < cnt; j++) {
                const int   sj  = __shfl_sync(0xffffffffu, s, j);
                const int   tj  = __shfl_sync(0xffffffffu, t, j);
                const float a0j = __shfl_sync(0xffffffffu, a0, j);
                const float a1j = __shfl_sync(0xffffffffu, a1, j);
                const float aj  = head ? a1j : a0j;
                float4 hv = *(const float4*)&g_h[(long)sj * HD + lane * 4];
                float4 rv = *(const float4*)&rp[tj * HD + lane * 4];
                acc.x += aj * (hv.x + rv.x);
                acc.y += aj * (hv.y + rv.y);
                acc.z += aj * (hv.z + rv.z);
                acc.w += aj * (hv.w + rv.w);
            }
        }
        acc.x = tanh_approx(acc.x);
        acc.y = tanh_approx(acc.y);
        acc.z = tanh_approx(acc.z);
        acc.w = tanh_approx(acc.w);
        *(float4*)&xout[(long)dst * HD + lane * 4] = acc;
    }
}

__global__ void k_gather(const int* __restrict__ sub, const float* __restrict__ xout,
                         float* __restrict__ sub_emb) {
    int b = blockIdx.x;
    int d = threadIdx.x;
    sub_emb[(long)b * HD + d] = xout[(long)sub[b] * HD + d];
}

// ---------------- launch ----------------
extern "C" void kernel_launch(void* const* d_in, const int* in_sizes, int n_in,
                              void* d_out, int out_size) {
    const int*   edge_index  = (const int*)d_in[0];
    const int*   edge_type   = (const int*)d_in[1];
    const int*   ent_feature = (const int*)d_in[3];
    const int*   sub         = (const int*)d_in[4];
    const float* id_embed    = (const float*)d_in[7];
    const float* gender_tab  = (const float*)d_in[8];
    const float* age_tab     = (const float*)d_in[9];
    const float* level_tab   = (const float*)d_in[10];
    const float* init_rel    = (const float*)d_in[11];
    const float* W           = (const float*)d_in[12];
    const float* Wr          = (const float*)d_in[13];
    const float* att_src     = (const float*)d_in[14];
    const float* att_dst     = (const float*)d_in[15];
    const float* Wrel        = (const float*)d_in[16];

    float* out     = (float*)d_out;
    float* sub_emb = out;                      // [2048,128]
    float* rout    = out + (long)BATCH * HD;   // [100,128]
    float* xout    = rout + (long)NREL * HD;   // [100000,128]

    const int smem_kh = (12800 + 2944 + 400 + 32) * (int)sizeof(float);
    cudaFuncSetAttribute(k_h, cudaFuncAttributeMaxDynamicSharedMemorySize, smem_kh);

    k_prep<<<223 + 49, 512>>>(gender_tab, age_tab, level_tab, init_rel, W, Wr, Wrel,
                              att_src, rout);
    k_h<<<444, 128, smem_kh>>>(id_embed, ent_feature, W, att_src, att_dst);
    k_deg<<<(N_EDGES + 255) / 256, 256>>>(edge_index);
    k_scan1<<<100, 256>>>();
    k_scan2<<<1, 32>>>();
    k_scan3<<<100, 256>>>();
    k_scatter<<<(N_EDGES + 255) / 256, 256>>>(edge_index, edge_type);
    k_agg<<<592, 256>>>(xout);
    k_gather<<<BATCH, 128>>>(sub, xout, sub_emb);
}

// round 4
// speedup vs baseline: 1.7424x; 1.0285x over previous
#include <cuda_runtime.h>

#define N_NODES 100000
#define N_EDGES 400000
#define BATCH   2048
#define HD      128
#define NREL    100

// ---------------- scratch ----------------
__device__ __align__(16) float g_h[(size_t)N_NODES * HD];
__device__ __align__(16) float g_ssrc[N_NODES * 2];
__device__ __align__(16) float g_sdst[N_NODES * 2];
__device__ __align__(16) float g_rproj[NREL * HD];
__device__ __align__(16) float g_srel[NREL * 2];
__device__ __align__(16) float g_catproj[23 * HD];
__device__ __align__(16) int   g_deg[N_NODES];
__device__ __align__(16) int   g_off[N_NODES + 1];
__device__ __align__(16) int   g_cur[N_NODES];
__device__ __align__(16) int   g_esrc[N_EDGES];
__device__ __align__(16) int   g_eet[N_EDGES];
__device__ int g_bsum[128];

__device__ __forceinline__ float tanh_approx(float x) {
    float y;
    asm("tanh.approx.f32 %0, %1;" : "=f"(y) : "f"(x));
    return y;
}
__device__ __forceinline__ void fma2(unsigned long long& acc, unsigned long long x,
                                     unsigned long long w) {
    asm("fma.rn.f32x2 %0, %1, %2, %0;" : "+l"(acc) : "l"(x), "l"(w));
}
__device__ __forceinline__ unsigned long long pack2(float a, float b) {
    unsigned long long r;
    asm("mov.b64 %0, {%1, %2};" : "=l"(r) : "r"(__float_as_uint(a)), "r"(__float_as_uint(b)));
    return r;
}
__device__ __forceinline__ void unpack2(unsigned long long v, float& a, float& b) {
    unsigned lo, hi;
    asm("mov.b64 {%0, %1}, %2;" : "=r"(lo), "=r"(hi) : "l"(v));
    a = __uint_as_float(lo);
    b = __uint_as_float(hi);
}

// ---------------- prep: small GEMMs (K-split) + zero degree counters ----------------
__global__ void k_prep(const float* __restrict__ gtab, const float* __restrict__ atab,
                       const float* __restrict__ ltab, const float* __restrict__ init_rel,
                       const float* __restrict__ W,    const float* __restrict__ Wr,
                       const float* __restrict__ Wrel, const float* __restrict__ att_src,
                       float* __restrict__ rout) {
    const int b   = blockIdx.x;
    const int tid = threadIdx.x;  // 512

    if (b >= 223) {
        int i = (b - 223) * 512 + tid;
        if (i < N_NODES / 4) ((int4*)g_deg)[i] = make_int4(0, 0, 0, 0);
        return;
    }

    const int d = tid & 127;
    const int s = tid >> 7;
    const float* arow;
    const float* Bmat;
    int klen;
    if (b < 100)       { arow = init_rel + b * 400;         Bmat = Wr;   klen = 400; }
    else if (b < 200)  { arow = init_rel + (b - 100) * 400; Bmat = Wrel; klen = 400; }
    else {
        int c = b - 200;
        if (c < 3)       { arow = gtab + c * 100;        Bmat = W + 100 * HD; }
        else if (c < 12) { arow = atab + (c - 3) * 100;  Bmat = W + 200 * HD; }
        else             { arow = ltab + (c - 12) * 100; Bmat = W + 300 * HD; }
        klen = 100;
    }
    const int span = klen >> 2;
    const int k0   = s * span;
    float acc = 0.f;
#pragma unroll 5
    for (int k = k0; k < k0 + span; k++) acc += arow[k] * Bmat[k * HD + d];

    __shared__ float part[512];
    part[tid] = acc;
    __syncthreads();
    float total = 0.f;
    if (tid < 128) {
        total = part[tid] + part[tid + 128] + part[tid + 256] + part[tid + 384];
        if (b < 100)      g_rproj[b * HD + d] = total;
        else if (b < 200) rout[(b - 100) * HD + d] = total;
        else              g_catproj[(b - 200) * HD + d] = total;
    }
    if (b < 100) {
        float p = (tid < 128) ? total * att_src[d] : 0.f;
#pragma unroll
        for (int o = 16; o > 0; o >>= 1) p += __shfl_xor_sync(0xffffffffu, p, o);
        __shared__ float ws[16];
        if ((tid & 31) == 0) ws[tid >> 5] = p;
        __syncthreads();
        if (tid == 0) {
            g_srel[b * 2 + 0] = ws[0] + ws[1];
            g_srel[b * 2 + 1] = ws[2] + ws[3];
        }
    }
}

// ---------------- h projection (f32x2 packed, 8 nodes/iter) + score scalars ----------------
__global__ void __launch_bounds__(128) k_h(
        const float* __restrict__ id_embed, const int* __restrict__ ent_feature,
        const float* __restrict__ W, const float* __restrict__ att_src,
        const float* __restrict__ att_dst) {
    extern __shared__ float sm[];
    float* Ws  = sm;            // 12800: W[0:100][128]
    float* cat = Ws + 12800;    // 2944
    float* sxT = cat + 2944;    // 800: id_embed transposed [k][node], 16B aligned
    float* red = sxT + 800;     // 64: [node][kind][warp]

    const int tid  = threadIdx.x;
    const int lane = tid & 31;
    const int w    = tid >> 5;
    for (int i = tid; i < 12800; i += 128) Ws[i] = W[i];
    for (int i = tid; i < 23 * HD; i += 128) cat[i] = g_catproj[i];
    const float a_s = att_src[tid];
    const float a_d = att_dst[tid];
    __syncthreads();

    for (int q = blockIdx.x; q < N_NODES / 8; q += gridDim.x) {
        const int n0 = q * 8;
        __syncthreads();  // everyone done with sxT/red of previous iter
        for (int i = tid; i < 800; i += 128) {
            int n = i / 100, k = i - n * 100;
            sxT[k * 8 + n] = id_embed[(long)n0 * 100 + i];
        }
        __syncthreads();

        unsigned long long acc0 = 0ull, acc1 = 0ull, acc2 = 0ull, acc3 = 0ull;
#pragma unroll 4
        for (int k = 0; k < 100; k++) {
            const ulonglong2* xp = (const ulonglong2*)&sxT[k * 8];
            ulonglong2 xa = xp[0];
            ulonglong2 xb = xp[1];
            float wv = Ws[k * 128 + tid];
            unsigned long long ww = pack2(wv, wv);
            fma2(acc0, xa.x, ww);
            fma2(acc1, xa.y, ww);
            fma2(acc2, xb.x, ww);
            fma2(acc3, xb.y, ww);
        }
        float accs[8];
        unpack2(acc0, accs[0], accs[1]);
        unpack2(acc1, accs[2], accs[3]);
        unpack2(acc2, accs[4], accs[5]);
        unpack2(acc3, accs[6], accs[7]);

#pragma unroll
        for (int i = 0; i < 8; i++) {
            const int n  = n0 + i;
            const int gf = ent_feature[n * 3 + 0];
            const int af = ent_feature[n * 3 + 1];
            const int lf = ent_feature[n * 3 + 2];
            float hv = accs[i] + cat[gf * 128 + tid] + cat[(3 + af) * 128 + tid]
                               + cat[(12 + lf) * 128 + tid];
            g_h[(long)n * HD + tid] = hv;

            float ps = hv * a_s, pd = hv * a_d;
#pragma unroll
            for (int o = 16; o > 0; o >>= 1) {
                ps += __shfl_xor_sync(0xffffffffu, ps, o);
                pd += __shfl_xor_sync(0xffffffffu, pd, o);
            }
            if (lane == 0) { red[i * 8 + w] = ps; red[i * 8 + 4 + w] = pd; }
        }
        __syncthreads();
        if (tid < 32) {
            const int i = tid >> 2;       // node 0..7
            const int q2 = tid & 3;       // kind*2 + head
            const int kind = q2 >> 1, h = q2 & 1;
            const float* base = red + i * 8 + kind * 4;
            float v = base[2 * h] + base[2 * h + 1];
            if (kind == 0) g_ssrc[(n0 + i) * 2 + h] = v;
            else           g_sdst[(n0 + i) * 2 + h] = v;
        }
    }
}

// ---------------- CSR build ----------------
__global__ void k_deg(const int* __restrict__ ei) {
    int e = blockIdx.x * 256 + threadIdx.x;
    if (e < N_EDGES) atomicAdd(&g_deg[ei[N_EDGES + e]], 1);
}

__global__ void k_scan1() {
    __shared__ int sred[256];
    const int tid = threadIdx.x;
    const int base = blockIdx.x * 1000;
    int s = 0;
    for (int i = tid; i < 1000; i += 256) s += g_deg[base + i];
    sred[tid] = s;
    __syncthreads();
    for (int o = 128; o > 0; o >>= 1) {
        if (tid < o) sred[tid] += sred[tid + o];
        __syncthreads();
    }
    if (tid == 0) g_bsum[blockIdx.x] = sred[0];
}

__global__ void k_scan2() {
    __shared__ int s[128];
    const int tid = threadIdx.x;
    int v = (tid < 100) ? g_bsum[tid] : 0;
    s[tid] = v;
    __syncthreads();
    for (int o = 1; o < 128; o <<= 1) {
        int add = (tid >= o) ? s[tid - o] : 0;
        __syncthreads();
        s[tid] += add;
        __syncthreads();
    }
    if (tid < 100) g_bsum[tid] = s[tid] - v;  // exclusive
    if (tid == 0) g_off[N_NODES] = N_EDGES;
}

__global__ void k_scan3() {
    __shared__ int ts[256];
    __shared__ int vals[1000];
    const int tid  = threadIdx.x;
    const int base = blockIdx.x * 1000;
    int v0 = 0, v1 = 0, v2 = 0, v3 = 0, tsum = 0;
    if (tid < 250) {
        v0 = g_deg[base + tid * 4 + 0];
        v1 = g_deg[base + tid * 4 + 1];
        v2 = g_deg[base + tid * 4 + 2];
        v3 = g_deg[base + tid * 4 + 3];
        tsum = v0 + v1 + v2 + v3;
    }
    ts[tid] = tsum;
    __syncthreads();
    for (int o = 1; o < 256; o <<= 1) {
        int add = (tid >= o) ? ts[tid - o] : 0;
        __syncthreads();
        ts[tid] += add;
        __syncthreads();
    }
    if (tid < 250) {
        int excl = ts[tid] - tsum + g_bsum[blockIdx.x];
        vals[tid * 4 + 0] = excl;
        vals[tid * 4 + 1] = excl + v0;
        vals[tid * 4 + 2] = excl + v0 + v1;
        vals[tid * 4 + 3] = excl + v0 + v1 + v2;
    }
    __syncthreads();
    for (int i = tid; i < 1000; i += 256) {
        g_off[base + i] = vals[i];
        g_cur[base + i] = vals[i];
    }
}

__global__ void k_scatter(const int* __restrict__ ei, const int* __restrict__ etyp) {
    int e = blockIdx.x * 256 + threadIdx.x;
    if (e >= N_EDGES) return;
    const int dst = ei[N_EDGES + e];
    int pos = atomicAdd(&g_cur[dst], 1);
    g_esrc[pos] = ei[e];
    g_eet[pos]  = etyp[e];
}

// ---------------- fused per-dst softmax + aggregation + tanh ----------------
__global__ void __launch_bounds__(256) k_agg(float* __restrict__ xout) {
    __shared__ float rp[NREL * HD];   // 51.2 KB
    __shared__ int   sm_s[8][32];
    __shared__ int   sm_t[8][32];
    __shared__ float sm_a[8][2][32];
    const int tid = threadIdx.x;      // 256
    for (int i = tid; i < NREL * HD; i += 256) rp[i] = g_rproj[i];
    __syncthreads();

    const int lane = tid & 31;
    const int wid  = tid >> 5;
    const int head = lane >> 4;       // dims lane*4.. : head = lane/16
    const int nwarps = gridDim.x * 8;

    for (int dst = blockIdx.x * 8 + wid; dst < N_NODES; dst += nwarps) {
        const int start = g_off[dst];
        const int end   = g_off[dst + 1];
        const int deg   = end - start;
        const float2 sd = ((const float2*)g_sdst)[dst];
        float4 acc = make_float4(0.f, 0.f, 0.f, 0.f);

        if (deg <= 32) {
            // single-pass: each lane owns one edge
            const int i = start + lane;
            const bool v = (i < end);
            int s = 0, t = 0;
            float l0 = -1e30f, l1 = -1e30f;
            if (v) {
                s = g_esrc[i]; t = g_eet[i];
                float2 ss = ((const float2*)g_ssrc)[s];
                float2 sr = ((const float2*)g_srel)[t];
                l0 = ss.x + sr.x + sd.x; l0 = (l0 > 0.f) ? l0 : 0.2f * l0;
                l1 = ss.y + sr.y + sd.y; l1 = (l1 > 0.f) ? l1 : 0.2f * l1;
            }
            float m0 = l0, m1 = l1;
#pragma unroll
            for (int o = 16; o > 0; o >>= 1) {
                m0 = fmaxf(m0, __shfl_xor_sync(0xffffffffu, m0, o));
                m1 = fmaxf(m1, __shfl_xor_sync(0xffffffffu, m1, o));
            }
            float e0 = v ? __expf(l0 - m0) : 0.f;
            float e1 = v ? __expf(l1 - m1) : 0.f;
            float d0 = e0, d1 = e1;
#pragma unroll
            for (int o = 16; o > 0; o >>= 1) {
                d0 += __shfl_xor_sync(0xffffffffu, d0, o);
                d1 += __shfl_xor_sync(0xffffffffu, d1, o);
            }
            sm_s[wid][lane] = s;
            sm_t[wid][lane] = t;
            sm_a[wid][0][lane] = e0 / (d0 + 1e-16f);
            sm_a[wid][1][lane] = e1 / (d1 + 1e-16f);
            __syncwarp();
            for (int j = 0; j < deg; j++) {
                const int   sj = sm_s[wid][j];
                const int   tj = sm_t[wid][j];
                const float aj = sm_a[wid][head][j];
                float4 hv = *(const float4*)&g_h[(long)sj * HD + lane * 4];
                float4 rv = *(const float4*)&rp[tj * HD + lane * 4];
                acc.x += aj * (hv.x + rv.x);
                acc.y += aj * (hv.y + rv.y);
                acc.z += aj * (hv.z + rv.z);
                acc.w += aj * (hv.w + rv.w);
            }
        } else {
            // fallback: 3-pass chunked
            float m0 = -1e30f, m1 = -1e30f;
            for (int i = start + lane; i < end; i += 32) {
                const int s = g_esrc[i], t = g_eet[i];
                float2 ss = ((const float2*)g_ssrc)[s];
                float2 sr = ((const float2*)g_srel)[t];
                float l0 = ss.x + sr.x + sd.x; l0 = (l0 > 0.f) ? l0 : 0.2f * l0;
                float l1 = ss.y + sr.y + sd.y; l1 = (l1 > 0.f) ? l1 : 0.2f * l1;
                m0 = fmaxf(m0, l0); m1 = fmaxf(m1, l1);
            }
#pragma unroll
            for (int o = 16; o > 0; o >>= 1) {
                m0 = fmaxf(m0, __shfl_xor_sync(0xffffffffu, m0, o));
                m1 = fmaxf(m1, __shfl_xor_sync(0xffffffffu, m1, o));
            }
            float d0 = 0.f, d1 = 0.f;
            for (int i = start + lane; i < end; i += 32) {
                const int s = g_esrc[i], t = g_eet[i];
                float2 ss = ((const float2*)g_ssrc)[s];
                float2 sr = ((const float2*)g_srel)[t];
                float l0 = ss.x + sr.x + sd.x; l0 = (l0 > 0.f) ? l0 : 0.2f * l0;
                float l1 = ss.y + sr.y + sd.y; l1 = (l1 > 0.f) ? l1 : 0.2f * l1;
                d0 += __expf(l0 - m0); d1 += __expf(l1 - m1);
            }
#pragma unroll
            for (int o = 16; o > 0; o >>= 1) {
                d0 += __shfl_xor_sync(0xffffffffu, d0, o);
                d1 += __shfl_xor_sync(0xffffffffu, d1, o);
            }
            const float inv0 = 1.f / (d0 + 1e-16f);
            const float inv1 = 1.f / (d1 + 1e-16f);
            for (int base = start; base < end; base += 32) {
                const int i = base + lane;
                int s = 0, t = 0;
                float a0 = 0.f, a1 = 0.f;
                if (i < end) {
                    s = g_esrc[i]; t = g_eet[i];
                    float2 ss = ((const float2*)g_ssrc)[s];
                    float2 sr = ((const float2*)g_srel)[t];
                    float l0 = ss.x + sr.x + sd.x; l0 = (l0 > 0.f) ? l0 : 0.2f * l0;
                    float l1 = ss.y + sr.y + sd.y; l1 = (l1 > 0.f) ? l1 : 0.2f * l1;
                    a0 = __expf(l0 - m0) * inv0;
                    a1 = __expf(l1 - m1) * inv1;
                }
                sm_s[wid][lane] = s;
                sm_t[wid][lane] = t;
                sm_a[wid][0][lane] = a0;
                sm_a[wid][1][lane] = a1;
                __syncwarp();
                const int cnt = min(32, end - base);
                for (int j = 0; j < cnt; j++) {
                    const int   sj = sm_s[wid][j];
                    const int   tj = sm_t[wid][j];
                    const float aj = sm_a[wid][head][j];
                    float4 hv = *(const float4*)&g_h[(long)sj * HD + lane * 4];
                    float4 rv = *(const float4*)&rp[tj * HD + lane * 4];
                    acc.x += aj * (hv.x + rv.x);
                    acc.y += aj * (hv.y + rv.y);
                    acc.z += aj * (hv.z + rv.z);
                    acc.w += aj * (hv.w + rv.w);
                }
                __syncwarp();
            }
        }
        acc.x = tanh_approx(acc.x);
        acc.y = tanh_approx(acc.y);
        acc.z = tanh_approx(acc.z);
        acc.w = tanh_approx(acc.w);
        *(float4*)&xout[(long)dst * HD + lane * 4] = acc;
    }
}

__global__ void k_gather(const int* __restrict__ sub, const float* __restrict__ xout,
                         float* __restrict__ sub_emb) {
    int b = blockIdx.x;
    int d = threadIdx.x;
    sub_emb[(long)b * HD + d] = xout[(long)sub[b] * HD + d];
}

// ---------------- launch ----------------
extern "C" void kernel_launch(void* const* d_in, const int* in_sizes, int n_in,
                              void* d_out, int out_size) {
    const int*   edge_index  = (const int*)d_in[0];
    const int*   edge_type   = (const int*)d_in[1];
    const int*   ent_feature = (const int*)d_in[3];
    const int*   sub         = (const int*)d_in[4];
    const float* id_embed    = (const float*)d_in[7];
    const float* gender_tab  = (const float*)d_in[8];
    const float* age_tab     = (const float*)d_in[9];
    const float* level_tab   = (const float*)d_in[10];
    const float* init_rel    = (const float*)d_in[11];
    const float* W           = (const float*)d_in[12];
    const float* Wr          = (const float*)d_in[13];
    const float* att_src     = (const float*)d_in[14];
    const float* att_dst     = (const float*)d_in[15];
    const float* Wrel        = (const float*)d_in[16];

    float* out     = (float*)d_out;
    float* sub_emb = out;
    float* rout    = out + (long)BATCH * HD;
    float* xout    = rout + (long)NREL * HD;

    const int smem_kh = (12800 + 2944 + 800 + 64) * (int)sizeof(float);  // 66432
    cudaFuncSetAttribute(k_h, cudaFuncAttributeMaxDynamicSharedMemorySize, smem_kh);

    k_prep<<<223 + 49, 512>>>(gender_tab, age_tab, level_tab, init_rel, W, Wr, Wrel,
                              att_src, rout);
    k_deg<<<(N_EDGES + 255) / 256, 256>>>(edge_index);
    k_scan1<<<100, 256>>>();
    k_h<<<444, 128, smem_kh>>>(id_embed, ent_feature, W, att_src, att_dst);  // profiled (idx 3)
    k_scan2<<<1, 128>>>();
    k_scan3<<<100, 256>>>();
    k_scatter<<<(N_EDGES + 255) / 256, 256>>>(edge_index, edge_type);
    k_agg<<<592, 256>>>(xout);
    k_gather<<<BATCH, 128>>>(sub, xout, sub_emb);
}

// round 5
// speedup vs baseline: 2.8643x; 1.6439x over previous
#include <cuda_runtime.h>

#define N_NODES 100000
#define N_EDGES 400000
#define BATCH   2048
#define HD      128
#define NREL    100

// ---------------- scratch ----------------
__device__ __align__(16) float g_h[(size_t)N_NODES * HD];
__device__ __align__(16) float g_ssrc[N_NODES * 2];
__device__ __align__(16) float g_sdst[N_NODES * 2];
__device__ __align__(16) float g_rproj[NREL * HD];
__device__ __align__(16) float g_srel[NREL * 2];
__device__ __align__(16) float g_catproj[23 * HD];
__device__ __align__(16) int   g_deg[N_NODES];
__device__ __align__(16) int   g_off[N_NODES + 1];
__device__ __align__(16) int   g_cur[N_NODES];
__device__ __align__(16) int   g_esrc[N_EDGES];
__device__ __align__(16) int   g_eet[N_EDGES];
__device__ int g_bsum[128];

__device__ __forceinline__ float tanh_approx(float x) {
    float y;
    asm("tanh.approx.f32 %0, %1;" : "=f"(y) : "f"(x));
    return y;
}
__device__ __forceinline__ void fma2(unsigned long long& acc, unsigned long long x,
                                     unsigned long long w) {
    asm("fma.rn.f32x2 %0, %1, %2, %0;" : "+l"(acc) : "l"(x), "l"(w));
}
__device__ __forceinline__ unsigned long long pack2(float a, float b) {
    unsigned long long r;
    asm("mov.b64 %0, {%1, %2};" : "=l"(r) : "r"(__float_as_uint(a)), "r"(__float_as_uint(b)));
    return r;
}
__device__ __forceinline__ void unpack2(unsigned long long v, float& a, float& b) {
    unsigned lo, hi;
    asm("mov.b64 {%0, %1}, %2;" : "=r"(lo), "=r"(hi) : "l"(v));
    a = __uint_as_float(lo);
    b = __uint_as_float(hi);
}

// ---------------- prep: small GEMMs (K-split) + zero degree counters ----------------
__global__ void k_prep(const float* __restrict__ gtab, const float* __restrict__ atab,
                       const float* __restrict__ ltab, const float* __restrict__ init_rel,
                       const float* __restrict__ W,    const float* __restrict__ Wr,
                       const float* __restrict__ Wrel, const float* __restrict__ att_src,
                       float* __restrict__ rout) {
    const int b   = blockIdx.x;
    const int tid = threadIdx.x;  // 512

    if (b >= 223) {
        int i = (b - 223) * 512 + tid;
        if (i < N_NODES / 4) ((int4*)g_deg)[i] = make_int4(0, 0, 0, 0);
        return;
    }

    const int d = tid & 127;
    const int s = tid >> 7;
    const float* arow;
    const float* Bmat;
    int klen;
    if (b < 100)       { arow = init_rel + b * 400;         Bmat = Wr;   klen = 400; }
    else if (b < 200)  { arow = init_rel + (b - 100) * 400; Bmat = Wrel; klen = 400; }
    else {
        int c = b - 200;
        if (c < 3)       { arow = gtab + c * 100;        Bmat = W + 100 * HD; }
        else if (c < 12) { arow = atab + (c - 3) * 100;  Bmat = W + 200 * HD; }
        else             { arow = ltab + (c - 12) * 100; Bmat = W + 300 * HD; }
        klen = 100;
    }
    const int span = klen >> 2;
    const int k0   = s * span;
    float acc = 0.f;
#pragma unroll 5
    for (int k = k0; k < k0 + span; k++) acc += arow[k] * Bmat[k * HD + d];

    __shared__ float part[512];
    part[tid] = acc;
    __syncthreads();
    float total = 0.f;
    if (tid < 128) {
        total = part[tid] + part[tid + 128] + part[tid + 256] + part[tid + 384];
        if (b < 100)      g_rproj[b * HD + d] = total;
        else if (b < 200) rout[(b - 100) * HD + d] = total;
        else              g_catproj[(b - 200) * HD + d] = total;
    }
    if (b < 100) {
        float p = (tid < 128) ? total * att_src[d] : 0.f;
#pragma unroll
        for (int o = 16; o > 0; o >>= 1) p += __shfl_xor_sync(0xffffffffu, p, o);
        __shared__ float ws[16];
        if ((tid & 31) == 0) ws[tid >> 5] = p;
        __syncthreads();
        if (tid == 0) {
            g_srel[b * 2 + 0] = ws[0] + ws[1];
            g_srel[b * 2 + 1] = ws[2] + ws[3];
        }
    }
}

// ---------------- h projection: register-tiled SGEMM 128x128 tile ----------------
// 256 threads; thread (tn=tid&15, tm=tid>>4) computes nodes tm*8..+7 x dims tn*8..+7.
__global__ void __launch_bounds__(256) k_h(
        const float* __restrict__ id_embed, const int* __restrict__ ent_feature,
        const float* __restrict__ W, const float* __restrict__ att_src,
        const float* __restrict__ att_dst) {
    extern __shared__ float sm[];
    float* sW   = sm;             // 12800: W[100][128]
    float* sX   = sW + 12800;     // 128*52: X[node][k-chunk] padded
    float* scat = sX + 6656;      // 2944
    int*   sft  = (int*)(scat + 2944);  // 384

    const int tid = threadIdx.x;
    const int tn  = tid & 15;
    const int tm  = tid >> 4;
    const int nbase = blockIdx.x * 128;

    for (int i = tid; i < 12800; i += 256) sW[i] = W[i];
    for (int i = tid; i < 2944; i += 256) scat[i] = g_catproj[i];
    for (int i = tid; i < 384; i += 256) {
        int node = nbase + i / 3;
        if (node >= N_NODES) node = N_NODES - 1;
        sft[i] = ent_feature[node * 3 + (i % 3)];
    }
    float as_[8], ad_[8];
#pragma unroll
    for (int d = 0; d < 8; d++) {
        as_[d] = att_src[tn * 8 + d];
        ad_[d] = att_dst[tn * 8 + d];
    }

    unsigned long long acc[8][4];
#pragma unroll
    for (int n = 0; n < 8; n++)
#pragma unroll
        for (int p = 0; p < 4; p++) acc[n][p] = 0ull;

#pragma unroll 1
    for (int c = 0; c < 2; c++) {
        __syncthreads();
        for (int i = tid; i < 6400; i += 256) {
            int r = i / 50, k = i - r * 50;
            int node = nbase + r;
            if (node >= N_NODES) node = N_NODES - 1;
            sX[r * 52 + k] = id_embed[(long)node * 100 + c * 50 + k];
        }
        __syncthreads();
        const float* wb = sW + c * 50 * 128;
        const float* xb = sX + tm * 8 * 52;
#pragma unroll 2
        for (int k = 0; k < 50; k++) {
            ulonglong2 wpa = *(const ulonglong2*)&wb[k * 128 + tn * 8];
            ulonglong2 wpb = *(const ulonglong2*)&wb[k * 128 + tn * 8 + 4];
#pragma unroll
            for (int n = 0; n < 8; n++) {
                float xv = xb[n * 52 + k];
                unsigned long long xx = pack2(xv, xv);
                fma2(acc[n][0], xx, wpa.x);
                fma2(acc[n][1], xx, wpa.y);
                fma2(acc[n][2], xx, wpb.x);
                fma2(acc[n][3], xx, wpb.y);
            }
        }
    }

    // epilogue: cat adds, store h, score dot products
#pragma unroll 1
    for (int n = 0; n < 8; n++) {
        const int nl   = tm * 8 + n;
        const int node = nbase + nl;
        const bool valid = (node < N_NODES);
        const int gf = sft[nl * 3 + 0];
        const int af = sft[nl * 3 + 1];
        const int lf = sft[nl * 3 + 2];
        float hv[8];
        unpack2(acc[n][0], hv[0], hv[1]);
        unpack2(acc[n][1], hv[2], hv[3]);
        unpack2(acc[n][2], hv[4], hv[5]);
        unpack2(acc[n][3], hv[6], hv[7]);
        const float* c0 = &scat[gf * 128 + tn * 8];
        const float* c1 = &scat[(3 + af) * 128 + tn * 8];
        const float* c2 = &scat[(12 + lf) * 128 + tn * 8];
        float4 c0a = *(const float4*)c0, c0b = *(const float4*)(c0 + 4);
        float4 c1a = *(const float4*)c1, c1b = *(const float4*)(c1 + 4);
        float4 c2a = *(const float4*)c2, c2b = *(const float4*)(c2 + 4);
        hv[0] += c0a.x + c1a.x + c2a.x;
        hv[1] += c0a.y + c1a.y + c2a.y;
        hv[2] += c0a.z + c1a.z + c2a.z;
        hv[3] += c0a.w + c1a.w + c2a.w;
        hv[4] += c0b.x + c1b.x + c2b.x;
        hv[5] += c0b.y + c1b.y + c2b.y;
        hv[6] += c0b.z + c1b.z + c2b.z;
        hv[7] += c0b.w + c1b.w + c2b.w;

        float ps = 0.f, pd = 0.f;
#pragma unroll
        for (int d = 0; d < 8; d++) {
            ps += hv[d] * as_[d];
            pd += hv[d] * ad_[d];
        }
        if (valid) {
            float* dst = &g_h[(long)node * HD + tn * 8];
            *(float4*)dst       = make_float4(hv[0], hv[1], hv[2], hv[3]);
            *(float4*)(dst + 4) = make_float4(hv[4], hv[5], hv[6], hv[7]);
        }
        // reduce over 8 lanes within each head-half (tn 0-7 = head0, 8-15 = head1)
#pragma unroll
        for (int o = 1; o < 8; o <<= 1) {
            ps += __shfl_xor_sync(0xffffffffu, ps, o);
            pd += __shfl_xor_sync(0xffffffffu, pd, o);
        }
        if ((tn & 7) == 0 && valid) {
            const int head = tn >> 3;
            g_ssrc[node * 2 + head] = ps;
            g_sdst[node * 2 + head] = pd;
        }
    }
}

// ---------------- CSR build ----------------
__global__ void k_deg(const int* __restrict__ ei) {
    int e = blockIdx.x * 256 + threadIdx.x;
    if (e < N_EDGES) atomicAdd(&g_deg[ei[N_EDGES + e]], 1);
}

__global__ void k_scan1() {
    __shared__ int sred[256];
    const int tid = threadIdx.x;
    const int base = blockIdx.x * 1000;
    int s = 0;
    for (int i = tid; i < 1000; i += 256) s += g_deg[base + i];
    sred[tid] = s;
    __syncthreads();
    for (int o = 128; o > 0; o >>= 1) {
        if (tid < o) sred[tid] += sred[tid + o];
        __syncthreads();
    }
    if (tid == 0) g_bsum[blockIdx.x] = sred[0];
}

__global__ void k_scan2() {
    __shared__ int s[128];
    const int tid = threadIdx.x;
    int v = (tid < 100) ? g_bsum[tid] : 0;
    s[tid] = v;
    __syncthreads();
    for (int o = 1; o < 128; o <<= 1) {
        int add = (tid >= o) ? s[tid - o] : 0;
        __syncthreads();
        s[tid] += add;
        __syncthreads();
    }
    if (tid < 100) g_bsum[tid] = s[tid] - v;
    if (tid == 0) g_off[N_NODES] = N_EDGES;
}

__global__ void k_scan3() {
    __shared__ int ts[256];
    __shared__ int vals[1000];
    const int tid  = threadIdx.x;
    const int base = blockIdx.x * 1000;
    int v0 = 0, v1 = 0, v2 = 0, v3 = 0, tsum = 0;
    if (tid < 250) {
        v0 = g_deg[base + tid * 4 + 0];
        v1 = g_deg[base + tid * 4 + 1];
        v2 = g_deg[base + tid * 4 + 2];
        v3 = g_deg[base + tid * 4 + 3];
        tsum = v0 + v1 + v2 + v3;
    }
    ts[tid] = tsum;
    __syncthreads();
    for (int o = 1; o < 256; o <<= 1) {
        int add = (tid >= o) ? ts[tid - o] : 0;
        __syncthreads();
        ts[tid] += add;
        __syncthreads();
    }
    if (tid < 250) {
        int excl = ts[tid] - tsum + g_bsum[blockIdx.x];
        vals[tid * 4 + 0] = excl;
        vals[tid * 4 + 1] = excl + v0;
        vals[tid * 4 + 2] = excl + v0 + v1;
        vals[tid * 4 + 3] = excl + v0 + v1 + v2;
    }
    __syncthreads();
    for (int i = tid; i < 1000; i += 256) {
        g_off[base + i] = vals[i];
        g_cur[base + i] = vals[i];
    }
}

__global__ void k_scatter(const int* __restrict__ ei, const int* __restrict__ etyp) {
    int e = blockIdx.x * 256 + threadIdx.x;
    if (e >= N_EDGES) return;
    const int dst = ei[N_EDGES + e];
    int pos = atomicAdd(&g_cur[dst], 1);
    g_esrc[pos] = ei[e];
    g_eet[pos]  = etyp[e];
}

// ---------------- fused per-dst softmax + aggregation + tanh ----------------
__global__ void __launch_bounds__(256) k_agg(float* __restrict__ xout) {
    __shared__ float rp[NREL * HD];
    __shared__ int   sm_s[8][32];
    __shared__ int   sm_t[8][32];
    __shared__ float sm_a[8][2][32];
    const int tid = threadIdx.x;
    for (int i = tid; i < NREL * HD; i += 256) rp[i] = g_rproj[i];
    __syncthreads();

    const int lane = tid & 31;
    const int wid  = tid >> 5;
    const int head = lane >> 4;
    const int nwarps = gridDim.x * 8;

    for (int dst = blockIdx.x * 8 + wid; dst < N_NODES; dst += nwarps) {
        const int start = g_off[dst];
        const int end   = g_off[dst + 1];
        const int deg   = end - start;
        const float2 sd = ((const float2*)g_sdst)[dst];
        float4 acc = make_float4(0.f, 0.f, 0.f, 0.f);

        if (deg <= 32) {
            const int i = start + lane;
            const bool v = (i < end);
            int s = 0, t = 0;
            float l0 = -1e30f, l1 = -1e30f;
            if (v) {
                s = g_esrc[i]; t = g_eet[i];
                float2 ss = ((const float2*)g_ssrc)[s];
                float2 sr = ((const float2*)g_srel)[t];
                l0 = ss.x + sr.x + sd.x; l0 = (l0 > 0.f) ? l0 : 0.2f * l0;
                l1 = ss.y + sr.y + sd.y; l1 = (l1 > 0.f) ? l1 : 0.2f * l1;
            }
            float m0 = l0, m1 = l1;
#pragma unroll
            for (int o = 16; o > 0; o >>= 1) {
                m0 = fmaxf(m0, __shfl_xor_sync(0xffffffffu, m0, o));
                m1 = fmaxf(m1, __shfl_xor_sync(0xffffffffu, m1, o));
            }
            float e0 = v ? __expf(l0 - m0) : 0.f;
            float e1 = v ? __expf(l1 - m1) : 0.f;
            float d0 = e0, d1 = e1;
#pragma unroll
            for (int o = 16; o > 0; o >>= 1) {
                d0 += __shfl_xor_sync(0xffffffffu, d0, o);
                d1 += __shfl_xor_sync(0xffffffffu, d1, o);
            }
            sm_s[wid][lane] = s;
            sm_t[wid][lane] = t;
            sm_a[wid][0][lane] = e0 / (d0 + 1e-16f);
            sm_a[wid][1][lane] = e1 / (d1 + 1e-16f);
            __syncwarp();
            for (int j = 0; j < deg; j++) {
                const int   sj = sm_s[wid][j];
                const int   tj = sm_t[wid][j];
                const float aj = sm_a[wid][head][j];
                float4 hv = *(const float4*)&g_h[(long)sj * HD + lane * 4];
                float4 rv = *(const float4*)&rp[tj * HD + lane * 4];
                acc.x += aj * (hv.x + rv.x);
                acc.y += aj * (hv.y + rv.y);
                acc.z += aj * (hv.z + rv.z);
                acc.w += aj * (hv.w + rv.w);
            }
        } else {
            float m0 = -1e30f, m1 = -1e30f;
            for (int i = start + lane; i < end; i += 32) {
                const int s = g_esrc[i], t = g_eet[i];
                float2 ss = ((const float2*)g_ssrc)[s];
                float2 sr = ((const float2*)g_srel)[t];
                float l0 = ss.x + sr.x + sd.x; l0 = (l0 > 0.f) ? l0 : 0.2f * l0;
                float l1 = ss.y + sr.y + sd.y; l1 = (l1 > 0.f) ? l1 : 0.2f * l1;
                m0 = fmaxf(m0, l0); m1 = fmaxf(m1, l1);
            }
#pragma unroll
            for (int o = 16; o > 0; o >>= 1) {
                m0 = fmaxf(m0, __shfl_xor_sync(0xffffffffu, m0, o));
                m1 = fmaxf(m1, __shfl_xor_sync(0xffffffffu, m1, o));
            }
            float d0 = 0.f, d1 = 0.f;
            for (int i = start + lane; i < end; i += 32) {
                const int s = g_esrc[i], t = g_eet[i];
                float2 ss = ((const float2*)g_ssrc)[s];
                float2 sr = ((const float2*)g_srel)[t];
                float l0 = ss.x + sr.x + sd.x; l0 = (l0 > 0.f) ? l0 : 0.2f * l0;
                float l1 = ss.y + sr.y + sd.y; l1 = (l1 > 0.f) ? l1 : 0.2f * l1;
                d0 += __expf(l0 - m0); d1 += __expf(l1 - m1);
            }
#pragma unroll
            for (int o = 16; o > 0; o >>= 1) {
                d0 += __shfl_xor_sync(0xffffffffu, d0, o);
                d1 += __shfl_xor_sync(0xffffffffu, d1, o);
            }
            const float inv0 = 1.f / (d0 + 1e-16f);
            const float inv1 = 1.f / (d1 + 1e-16f);
            for (int base = start; base < end; base += 32) {
                const int i = base + lane;
                int s = 0, t = 0;
                float a0 = 0.f, a1 = 0.f;
                if (i < end) {
                    s = g_esrc[i]; t = g_eet[i];
                    float2 ss = ((const float2*)g_ssrc)[s];
                    float2 sr = ((const float2*)g_srel)[t];
                    float l0 = ss.x + sr.x + sd.x; l0 = (l0 > 0.f) ? l0 : 0.2f * l0;
                    float l1 = ss.y + sr.y + sd.y; l1 = (l1 > 0.f) ? l1 : 0.2f * l1;
                    a0 = __expf(l0 - m0) * inv0;
                    a1 = __expf(l1 - m1) * inv1;
                }
                sm_s[wid][lane] = s;
                sm_t[wid][lane] = t;
                sm_a[wid][0][lane] = a0;
                sm_a[wid][1][lane] = a1;
                __syncwarp();
                const int cnt = min(32, end - base);
                for (int j = 0; j < cnt; j++) {
                    const int   sj = sm_s[wid][j];
                    const int   tj = sm_t[wid][j];
                    const float aj = sm_a[wid][head][j];
                    float4 hv = *(const float4*)&g_h[(long)sj * HD + lane * 4];
                    float4 rv = *(const float4*)&rp[tj * HD + lane * 4];
                    acc.x += aj * (hv.x + rv.x);
                    acc.y += aj * (hv.y + rv.y);
                    acc.z += aj * (hv.z + rv.z);
                    acc.w += aj * (hv.w + rv.w);
                }
                __syncwarp();
            }
        }
        acc.x = tanh_approx(acc.x);
        acc.y = tanh_approx(acc.y);
        acc.z = tanh_approx(acc.z);
        acc.w = tanh_approx(acc.w);
        *(float4*)&xout[(long)dst * HD + lane * 4] = acc;
    }
}

__global__ void k_gather(const int* __restrict__ sub, const float* __restrict__ xout,
                         float* __restrict__ sub_emb) {
    int b = blockIdx.x;
    int d = threadIdx.x;
    sub_emb[(long)b * HD + d] = xout[(long)sub[b] * HD + d];
}

// ---------------- launch ----------------
extern "C" void kernel_launch(void* const* d_in, const int* in_sizes, int n_in,
                              void* d_out, int out_size) {
    const int*   edge_index  = (const int*)d_in[0];
    const int*   edge_type   = (const int*)d_in[1];
    const int*   ent_feature = (const int*)d_in[3];
    const int*   sub         = (const int*)d_in[4];
    const float* id_embed    = (const float*)d_in[7];
    const float* gender_tab  = (const float*)d_in[8];
    const float* age_tab     = (const float*)d_in[9];
    const float* level_tab   = (const float*)d_in[10];
    const float* init_rel    = (const float*)d_in[11];
    const float* W           = (const float*)d_in[12];
    const float* Wr          = (const float*)d_in[13];
    const float* att_src     = (const float*)d_in[14];
    const float* att_dst     = (const float*)d_in[15];
    const float* Wrel        = (const float*)d_in[16];

    float* out     = (float*)d_out;
    float* sub_emb = out;
    float* rout    = out + (long)BATCH * HD;
    float* xout    = rout + (long)NREL * HD;

    // smem: W 12800 + X 6656 + cat 2944 floats + 384 ints = 91136 B
    const int smem_kh = (12800 + 6656 + 2944) * 4 + 384 * 4;
    cudaFuncSetAttribute(k_h, cudaFuncAttributeMaxDynamicSharedMemorySize, smem_kh);

    k_prep<<<223 + 49, 512>>>(gender_tab, age_tab, level_tab, init_rel, W, Wr, Wrel,
                              att_src, rout);
    k_deg<<<(N_EDGES + 255) / 256, 256>>>(edge_index);
    k_scan1<<<100, 256>>>();
    k_h<<<(N_NODES + 127) / 128, 256, smem_kh>>>(id_embed, ent_feature, W,
                                                 att_src, att_dst);  // profiled idx 3
    k_scan2<<<1, 128>>>();
    k_scan3<<<100, 256>>>();
    k_scatter<<<(N_EDGES + 255) / 256, 256>>>(edge_index, edge_type);
    k_agg<<<592, 256>>>(xout);
    k_gather<<<BATCH, 128>>>(sub, xout, sub_emb);
}